// round 11
// baseline (speedup 1.0000x reference)
#include <cuda_runtime.h>
#include <cuda_fp16.h>
#include <cstdint>

// Fixed shapes: z (65536,256) fp32, centroids (256,256) fp32
#define DDIM   256
#define KCENT  256
#define BM     64           // rows per tile in pass1
#define NTHR   256
#define GRID1  152          // persistent CTAs (GB300: 152 SMs)
#define RS     264          // smem row stride in halfs (256 + 8 pad)

// ---------------- device scratch (static, no allocation) ----------------
__device__ float g_partC[KCENT * GRID1];                // per-CTA colsum partials [col][cta]
__device__ float g_rcol[KCENT];                         // 1 / colsum(q)

// ---------------- helpers ----------------
__device__ __forceinline__ uint32_t smem_u32(const void* p) {
    uint32_t a;
    asm("{ .reg .u64 t; cvta.to.shared.u64 t, %1; cvt.u32.u64 %0, t; }"
        : "=r"(a) : "l"(p));
    return a;
}

__device__ __forceinline__ void ldsm4(uint32_t& r0, uint32_t& r1,
                                      uint32_t& r2, uint32_t& r3, uint32_t addr) {
    asm volatile("ldmatrix.sync.aligned.m8n8.x4.shared.b16 {%0,%1,%2,%3}, [%4];"
                 : "=r"(r0), "=r"(r1), "=r"(r2), "=r"(r3) : "r"(addr));
}

__device__ __forceinline__ void mma16816(float* d, uint32_t a0, uint32_t a1,
                                         uint32_t a2, uint32_t a3,
                                         uint32_t b0, uint32_t b1) {
    asm volatile(
        "mma.sync.aligned.m16n8k16.row.col.f32.f16.f16.f32 "
        "{%0,%1,%2,%3}, {%4,%5,%6,%7}, {%8,%9}, {%0,%1,%2,%3};"
        : "+f"(d[0]), "+f"(d[1]), "+f"(d[2]), "+f"(d[3])
        : "r"(a0), "r"(a1), "r"(a2), "r"(a3), "r"(b0), "r"(b1));
}

// ---------------- kernel 1: persistent GEMM + Student-t + rownorm -> q ----------------
// SMEM layout (bytes):
//   [0)      rowpart 4*64 f  = 1024
//   [1024)   colpart 2*256 f = 2048
//   [3072)   z2s     64 f    = 256
//   [3328)   rinv    64 f    = 256
//   [3584)   c2s     256 f   = 1024
//   [4608)   z2p     64*65 f = 16640
//   [21248)  A tile  64 x RS halfs  = 33792
//   [55040)  B tile  256 x RS halfs = 135168   total = 190208
#define SM_ROWPART 0
#define SM_COLPART 1024
#define SM_Z2      3072
#define SM_RINV    3328
#define SM_C2      3584
#define SM_Z2P     4608
#define SM_A       21248
#define SM_B       55040
#define SMEM_TOTAL 190208

__device__ __forceinline__ void ldgA(const float* __restrict__ z, int tile,
                                     int tid, float4* pregs) {
    const float4* zf = (const float4*)z + (size_t)tile * (BM * 64);
    #pragma unroll
    for (int t = 0; t < 16; t++) pregs[t] = zf[tid + t * NTHR];
}

__device__ __forceinline__ void convertA(char* smem, int tid, const float4* pregs) {
    float* z2p = (float*)(smem + SM_Z2P);
    int s = tid & 63;
    #pragma unroll
    for (int t = 0; t < 16; t++) {
        int i = tid + t * NTHR;
        int r = i >> 6;                 // row
        int c4 = (i & 63) << 2;         // starting half-col
        float4 f = pregs[t];
        __half2 h0 = __floats2half2_rn(f.x, f.y);
        __half2 h1 = __floats2half2_rn(f.z, f.w);
        uint2 u;
        u.x = *(const uint32_t*)&h0;
        u.y = *(const uint32_t*)&h1;
        *(uint2*)(smem + SM_A + (r * RS + c4) * 2) = u;
        z2p[r * 65 + s] = f.x * f.x + f.y * f.y + f.z * f.z + f.w * f.w;
    }
}

__global__ void __launch_bounds__(NTHR, 1) pass1_kernel(const float* __restrict__ z,
                                                        const float* __restrict__ cent,
                                                        float* __restrict__ out,
                                                        int nrows) {
    extern __shared__ char smem[];
    uint32_t sb = smem_u32(smem);
    int tid = threadIdx.x;
    int wid = tid >> 5, lane = tid & 31;
    int g = lane >> 2, tig = lane & 3;
    int wm = wid >> 2, wn = wid & 3;   // 2 M-warps x 4 N-warps
    int ntiles = nrows / BM;           // 1024

    // ---- B: centroids fp32 -> fp16 smem (once per CTA, fused prep) ----
    const float4* cf = (const float4*)cent;
    #pragma unroll
    for (int t = 0; t < 32; t++) {
        int i = tid + t * NTHR;                   // 8192 chunks of 8 halfs
        int row = i >> 5, c8 = (i & 31) << 3;
        float4 f0 = cf[i * 2], f1 = cf[i * 2 + 1];
        __half2 h0 = __floats2half2_rn(f0.x, f0.y);
        __half2 h1 = __floats2half2_rn(f0.z, f0.w);
        __half2 h2 = __floats2half2_rn(f1.x, f1.y);
        __half2 h3 = __floats2half2_rn(f1.z, f1.w);
        uint4 u;
        u.x = *(const uint32_t*)&h0;
        u.y = *(const uint32_t*)&h1;
        u.z = *(const uint32_t*)&h2;
        u.w = *(const uint32_t*)&h3;
        *(uint4*)(smem + SM_B + (row * RS + c8) * 2) = u;
    }
    {   // exact fp32 c2: one full centroid row per thread (L2-broadcast hot)
        const float4* cr = cf + tid * 64;
        float s = 0.f;
        #pragma unroll
        for (int j = 0; j < 64; j++) {
            float4 f = cr[j];
            s += f.x * f.x + f.y * f.y + f.z * f.z + f.w * f.w;
        }
        ((float*)(smem + SM_C2))[tid] = s;
    }

    float cpacc = 0.f;                 // per-thread (=per-column) running partial
    float4 pregs[16];

    uint32_t a_base = sb + SM_A + ((wm * 32 + (lane & 15)) * RS + (lane >> 4) * 8) * 2;
    uint32_t b_base;
    {
        int sel = lane >> 3;
        int n = wn * 64 + ((sel >> 1) << 3) + (lane & 7);
        int koff = (sel & 1) << 3;
        b_base = sb + SM_B + (n * RS + koff) * 2;
    }

    int t = blockIdx.x;
    // prologue: stage tile t (grid <= ntiles always)
    ldgA(z, t, tid, pregs);
    convertA(smem, tid, pregs);
    __syncthreads();
    if (tid < 64) {
        const float* z2p = (float*)(smem + SM_Z2P) + tid * 65;
        float s = 0.f;
        #pragma unroll
        for (int c = 0; c < 64; c++) s += z2p[c];
        ((float*)(smem + SM_Z2))[tid] = s;
    }
    __syncthreads();

    while (true) {
        int tn = t + GRID1;
        bool has_next = tn < ntiles;
        if (has_next) ldgA(z, tn, tid, pregs);   // prefetch into regs

        // z2 for current tile into regs (smem slot reused for next tile)
        float* z2s = (float*)(smem + SM_Z2);
        float z2v[4];
        #pragma unroll
        for (int i = 0; i < 4; i++) {
            int mt = i >> 1, hh = i & 1;
            z2v[i] = z2s[wm * 32 + mt * 16 + hh * 8 + g];
        }

        // ---- MMA: warp tile 32(M) x 64(N), K=256 ----
        float acc[2][8][4];
        #pragma unroll
        for (int mt = 0; mt < 2; mt++)
            #pragma unroll
            for (int nt = 0; nt < 8; nt++)
                #pragma unroll
                for (int f = 0; f < 4; f++) acc[mt][nt][f] = 0.f;

        #pragma unroll
        for (int kb = 0; kb < 16; kb++) {
            uint32_t a0, a1, a2, a3, a4, a5, a6, a7;
            ldsm4(a0, a1, a2, a3, a_base + kb * 32);
            ldsm4(a4, a5, a6, a7, a_base + 16 * RS * 2 + kb * 32);
            #pragma unroll
            for (int nt2 = 0; nt2 < 4; nt2++) {
                uint32_t b0, b1, b2, b3;
                ldsm4(b0, b1, b2, b3, b_base + nt2 * 16 * RS * 2 + kb * 32);
                mma16816(acc[0][2 * nt2],     a0, a1, a2, a3, b0, b1);
                mma16816(acc[0][2 * nt2 + 1], a0, a1, a2, a3, b2, b3);
                mma16816(acc[1][2 * nt2],     a4, a5, a6, a7, b0, b1);
                mma16816(acc[1][2 * nt2 + 1], a4, a5, a6, a7, b2, b3);
            }
        }
        __syncthreads();            // everyone done reading A smem

        // stage next tile into A smem + z2 partials (frees pregs)
        if (has_next) convertA(smem, tid, pregs);
        __syncthreads();
        if (has_next && tid < 64) {
            const float* z2p = (float*)(smem + SM_Z2P) + tid * 65;
            float s = 0.f;
            #pragma unroll
            for (int c = 0; c < 64; c++) s += z2p[c];
            ((float*)(smem + SM_Z2))[tid] = s;
        }

        // ---- epilogue: Student-t + row sums ----
        float* c2s = (float*)(smem + SM_C2);
        float rs[4] = {0.f, 0.f, 0.f, 0.f};
        #pragma unroll
        for (int mt = 0; mt < 2; mt++)
            #pragma unroll
            for (int nt = 0; nt < 8; nt++)
                #pragma unroll
                for (int f = 0; f < 4; f++) {
                    int hh = f >> 1, par = f & 1;
                    int col = wn * 64 + nt * 8 + tig * 2 + par;
                    float sse = fmaxf(fmaf(-2.f, acc[mt][nt][f],
                                           z2v[mt * 2 + hh] + c2s[col]), 0.f);
                    float v = __fdividef(1.f, 1.f + sse);
                    acc[mt][nt][f] = v;
                    rs[mt * 2 + hh] += v;
                }
        #pragma unroll
        for (int i = 0; i < 4; i++) {
            rs[i] += __shfl_xor_sync(0xffffffffu, rs[i], 1);
            rs[i] += __shfl_xor_sync(0xffffffffu, rs[i], 2);
        }
        float* rp = (float*)(smem + SM_ROWPART);
        if (tig == 0) {
            #pragma unroll
            for (int i = 0; i < 4; i++) {
                int mt = i >> 1, hh = i & 1;
                rp[wn * 64 + wm * 32 + mt * 16 + hh * 8 + g] = rs[i];
            }
        }
        __syncthreads();

        if (tid < 64) {
            float s = rp[tid] + rp[64 + tid] + rp[128 + tid] + rp[192 + tid];
            ((float*)(smem + SM_RINV))[tid] = __fdividef(1.f, s);
        }
        __syncthreads();

        float* rinv_s = (float*)(smem + SM_RINV);
        float riv[4];
        #pragma unroll
        for (int i = 0; i < 4; i++) {
            int mt = i >> 1, hh = i & 1;
            riv[i] = rinv_s[wm * 32 + mt * 16 + hh * 8 + g];
        }

        // write normalized q + per-tile column partials
        float cp[16];
        #pragma unroll
        for (int j = 0; j < 16; j++) cp[j] = 0.f;

        float* qbase = out + (size_t)nrows * KCENT + (size_t)t * BM * KCENT;
        #pragma unroll
        for (int mt = 0; mt < 2; mt++)
            #pragma unroll
            for (int hh = 0; hh < 2; hh++) {
                int rloc = wm * 32 + mt * 16 + hh * 8 + g;
                float* qrow = qbase + (size_t)rloc * KCENT + wn * 64;
                float ri = riv[mt * 2 + hh];
                #pragma unroll
                for (int nt = 0; nt < 8; nt++) {
                    float2 v2;
                    v2.x = acc[mt][nt][hh * 2]     * ri;
                    v2.y = acc[mt][nt][hh * 2 + 1] * ri;
                    *(float2*)(qrow + nt * 8 + tig * 2) = v2;
                    cp[nt * 2]     += v2.x;
                    cp[nt * 2 + 1] += v2.y;
                }
            }
        #pragma unroll
        for (int j = 0; j < 16; j++) {
            cp[j] += __shfl_xor_sync(0xffffffffu, cp[j], 4);
            cp[j] += __shfl_xor_sync(0xffffffffu, cp[j], 8);
            cp[j] += __shfl_xor_sync(0xffffffffu, cp[j], 16);
        }
        float* cps = (float*)(smem + SM_COLPART);
        if (g == 0) {
            #pragma unroll
            for (int nt = 0; nt < 8; nt++) {
                cps[wm * 256 + wn * 64 + nt * 8 + tig * 2]     = cp[nt * 2];
                cps[wm * 256 + wn * 64 + nt * 8 + tig * 2 + 1] = cp[nt * 2 + 1];
            }
        }
        __syncthreads();
        cpacc += cps[tid] + cps[256 + tid];   // accumulate across tiles (deterministic)

        if (!has_next) break;
        t = tn;
    }
    // one partial write per CTA
    g_partC[(size_t)tid * GRID1 + blockIdx.x] = cpacc;
}

// ---------------- kernel 2: column-sum reduction (one warp per column) ----------------
__global__ void reduceT_kernel() {     // grid 32, 256 thr
    int w = threadIdx.x >> 5, lane = threadIdx.x & 31;
    int col = blockIdx.x * 8 + w;
    const float* src = g_partC + (size_t)col * GRID1;
    float s = 0.f;
    for (int j = lane; j < GRID1; j += 32) s += src[j];
    #pragma unroll
    for (int o = 16; o; o >>= 1) s += __shfl_xor_sync(0xffffffffu, s, o);
    if (lane == 0) g_rcol[col] = __fdividef(1.f, s);
}

// ---------------- kernel 3: p = rownorm(q^2 / colsum) ----------------
__global__ void __launch_bounds__(256) pass2_kernel(float* __restrict__ out, int nrows) {
    int tid = threadIdx.x, w = tid >> 5, lane = tid & 31;
    const float* q = out + (size_t)nrows * KCENT;
    float* p = out;
    float rcl[8];
    #pragma unroll
    for (int t = 0; t < 8; t++) rcl[t] = g_rcol[lane * 8 + t];

    size_t row0 = (size_t)blockIdx.x * 32 + w * 4;
    float4 a[4], b[4];
    #pragma unroll
    for (int i = 0; i < 4; i++) {
        const float4* qr = (const float4*)(q + (row0 + i) * KCENT);
        a[i] = __ldcs(qr + lane * 2);
        b[i] = __ldcs(qr + lane * 2 + 1);
    }
    float s[4];
    #pragma unroll
    for (int i = 0; i < 4; i++) {
        a[i].x = a[i].x * a[i].x * rcl[0];
        a[i].y = a[i].y * a[i].y * rcl[1];
        a[i].z = a[i].z * a[i].z * rcl[2];
        a[i].w = a[i].w * a[i].w * rcl[3];
        b[i].x = b[i].x * b[i].x * rcl[4];
        b[i].y = b[i].y * b[i].y * rcl[5];
        b[i].z = b[i].z * b[i].z * rcl[6];
        b[i].w = b[i].w * b[i].w * rcl[7];
        s[i] = ((a[i].x + a[i].y) + (a[i].z + a[i].w))
             + ((b[i].x + b[i].y) + (b[i].z + b[i].w));
    }
    #pragma unroll
    for (int o = 16; o; o >>= 1) {
        #pragma unroll
        for (int i = 0; i < 4; i++) s[i] += __shfl_xor_sync(0xffffffffu, s[i], o);
    }
    #pragma unroll
    for (int i = 0; i < 4; i++) {
        float rinv = __fdividef(1.f, s[i]);
        float4 pa, pb;
        pa.x = a[i].x * rinv; pa.y = a[i].y * rinv;
        pa.z = a[i].z * rinv; pa.w = a[i].w * rinv;
        pb.x = b[i].x * rinv; pb.y = b[i].y * rinv;
        pb.z = b[i].z * rinv; pb.w = b[i].w * rinv;
        float4* pr = (float4*)(p + (row0 + i) * KCENT);
        __stcs(pr + lane * 2, pa);
        __stcs(pr + lane * 2 + 1, pb);
    }
}

// ---------------- launch ----------------
extern "C" void kernel_launch(void* const* d_in, const int* in_sizes, int n_in,
                              void* d_out, int out_size) {
    const float* z = (const float*)d_in[0];
    const float* cent = (const float*)d_in[1];
    float* out = (float*)d_out;
    int nrows = in_sizes[0] / DDIM;          // 65536

    cudaFuncSetAttribute(pass1_kernel,
                         cudaFuncAttributeMaxDynamicSharedMemorySize, SMEM_TOTAL);

    pass1_kernel<<<GRID1, NTHR, SMEM_TOTAL>>>(z, cent, out, nrows);
    reduceT_kernel<<<32, 256>>>();
    pass2_kernel<<<nrows / 32, 256>>>(out, nrows);
}

// round 12
// speedup vs baseline: 1.0992x; 1.0992x over previous
#include <cuda_runtime.h>
#include <cuda_fp16.h>
#include <cstdint>

// Fixed shapes: z (65536,256) fp32, centroids (256,256) fp32
#define DDIM   256
#define KCENT  256
#define BM     64           // rows per tile in pass1
#define NTHR   256
#define GRID1  152          // persistent CTAs (GB300: 152 SMs)
#define RS     264          // smem row stride in halfs (256 + 8 pad)

// ---------------- device scratch (static, no allocation) ----------------
__device__ __align__(16) __half g_cbuf[KCENT * DDIM];   // centroids fp16
__device__ float g_c2[KCENT];                           // ||c_k||^2 fp32
__device__ float g_partC[KCENT * GRID1];                // per-CTA colsum partials [col][cta]
__device__ float g_rcol[KCENT];                         // 1 / colsum(q)

// ---------------- helpers ----------------
__device__ __forceinline__ uint32_t smem_u32(const void* p) {
    uint32_t a;
    asm("{ .reg .u64 t; cvta.to.shared.u64 t, %1; cvt.u32.u64 %0, t; }"
        : "=r"(a) : "l"(p));
    return a;
}

__device__ __forceinline__ void ldsm4(uint32_t& r0, uint32_t& r1,
                                      uint32_t& r2, uint32_t& r3, uint32_t addr) {
    asm volatile("ldmatrix.sync.aligned.m8n8.x4.shared.b16 {%0,%1,%2,%3}, [%4];"
                 : "=r"(r0), "=r"(r1), "=r"(r2), "=r"(r3) : "r"(addr));
}

__device__ __forceinline__ void mma16816(float* d, uint32_t a0, uint32_t a1,
                                         uint32_t a2, uint32_t a3,
                                         uint32_t b0, uint32_t b1) {
    asm volatile(
        "mma.sync.aligned.m16n8k16.row.col.f32.f16.f16.f32 "
        "{%0,%1,%2,%3}, {%4,%5,%6,%7}, {%8,%9}, {%0,%1,%2,%3};"
        : "+f"(d[0]), "+f"(d[1]), "+f"(d[2]), "+f"(d[3])
        : "r"(a0), "r"(a1), "r"(a2), "r"(a3), "r"(b0), "r"(b1));
}

// ---------------- kernel 0: centroid fp32 -> fp16 + exact c2 ----------------
__global__ void prep_kernel(const float* __restrict__ cent) {
    int k = blockIdx.x, t = threadIdx.x;
    float v = cent[k * DDIM + t];
    g_cbuf[k * DDIM + t] = __float2half_rn(v);
    float s = v * v;
    #pragma unroll
    for (int o = 16; o; o >>= 1) s += __shfl_xor_sync(0xffffffffu, s, o);
    __shared__ float ws[8];
    if ((t & 31) == 0) ws[t >> 5] = s;
    __syncthreads();
    if (t == 0) {
        float tot = 0.f;
        #pragma unroll
        for (int j = 0; j < 8; j++) tot += ws[j];
        g_c2[k] = tot;
    }
}

// ---------------- kernel 1: persistent GEMM + Student-t + rownorm -> q ----------------
// SMEM layout (bytes):
//   [0)      rowpart 4*64 f      = 1024
//   [1024)   colpart 2*256 f     = 2048
//   [3072)   z2s     2*64 f      = 512
//   [3584)   rinv    64 f        = 256
//   [3840)   c2s     256 f       = 1024
//   [4864)   z2p     64*65 f     = 16640
//   [21504)  A0 tile 64 x RS h   = 33792
//   [55296)  A1 tile 64 x RS h   = 33792
//   [89088)  B tile  256 x RS h  = 135168    total = 224256
#define SM_ROWPART 0
#define SM_COLPART 1024
#define SM_Z2      3072
#define SM_RINV    3584
#define SM_C2      3840
#define SM_Z2P     4864
#define SM_A0      21504u
#define SM_A1      55296u
#define SM_B       89088u
#define SMEM_TOTAL 224256

__device__ __forceinline__ void ldgA(const float* __restrict__ z, int tile,
                                     int tid, float4* pregs) {
    const float4* zf = (const float4*)z + (size_t)tile * (BM * 64);
    #pragma unroll
    for (int t = 0; t < 16; t++) pregs[t] = zf[tid + t * NTHR];
}

__device__ __forceinline__ void convertA(char* smem, uint32_t abase, int tid,
                                         const float4* pregs) {
    float* z2p = (float*)(smem + SM_Z2P);
    int s = tid & 63;
    #pragma unroll
    for (int t = 0; t < 16; t++) {
        int i = tid + t * NTHR;
        int r = i >> 6;                 // row
        int c4 = (i & 63) << 2;         // starting half-col
        float4 f = pregs[t];
        __half2 h0 = __floats2half2_rn(f.x, f.y);
        __half2 h1 = __floats2half2_rn(f.z, f.w);
        uint2 u;
        u.x = *(const uint32_t*)&h0;
        u.y = *(const uint32_t*)&h1;
        *(uint2*)(smem + abase + (r * RS + c4) * 2) = u;
        z2p[r * 65 + s] = f.x * f.x + f.y * f.y + f.z * f.z + f.w * f.w;
    }
}

__global__ void __launch_bounds__(NTHR, 1) pass1_kernel(const float* __restrict__ z,
                                                        float* __restrict__ out,
                                                        int nrows) {
    extern __shared__ char smem[];
    uint32_t sb = smem_u32(smem);
    int tid = threadIdx.x;
    int wid = tid >> 5, lane = tid & 31;
    int g = lane >> 2, tig = lane & 3;
    int wm = wid >> 2, wn = wid & 3;   // 2 M-warps x 4 N-warps
    int ntiles = nrows / BM;           // 1024

    // ---- B: centroids fp16 from staging -> smem (once per CTA) ----
    const uint4* cb = (const uint4*)g_cbuf;       // 8 halfs per uint4
    #pragma unroll
    for (int t = 0; t < 32; t++) {
        int i = tid + t * NTHR;                   // 8192 uint4
        int row = i >> 5, c8 = (i & 31) << 3;
        *(uint4*)(smem + SM_B + (row * RS + c8) * 2) = cb[i];
    }
    ((float*)(smem + SM_C2))[tid] = g_c2[tid];
    // init colpart accumulators
    ((float*)(smem + SM_COLPART))[tid] = 0.f;
    ((float*)(smem + SM_COLPART))[tid + 256] = 0.f;

    float4 pregs[16];

    uint32_t a_base0 = sb + SM_A0 + ((wm * 32 + (lane & 15)) * RS + (lane >> 4) * 8) * 2;
    uint32_t a_stride_buf = SM_A1 - SM_A0;
    uint32_t b_base;
    {
        int sel = lane >> 3;
        int n = wn * 64 + ((sel >> 1) << 3) + (lane & 7);
        int koff = (sel & 1) << 3;
        b_base = sb + SM_B + (n * RS + koff) * 2;
    }

    int t = blockIdx.x;
    int buf = 0;
    // prologue: stage tile t into buf0
    ldgA(z, t, tid, pregs);
    convertA(smem, SM_A0, tid, pregs);
    __syncthreads();
    if (tid < 64) {
        const float* z2p = (float*)(smem + SM_Z2P) + tid * 65;
        float s = 0.f;
        #pragma unroll
        for (int c = 0; c < 64; c++) s += z2p[c];
        ((float*)(smem + SM_Z2))[tid] = s;   // z2s[0]
    }
    __syncthreads();

    while (true) {
        int tn = t + GRID1;
        bool has_next = tn < ntiles;
        if (has_next) ldgA(z, tn, tid, pregs);   // prefetch into regs

        // z2 for current tile into regs
        float* z2s = (float*)(smem + SM_Z2) + buf * 64;
        float z2v[4];
        #pragma unroll
        for (int i = 0; i < 4; i++) {
            int mt = i >> 1, hh = i & 1;
            z2v[i] = z2s[wm * 32 + mt * 16 + hh * 8 + g];
        }

        // ---- MMA: warp tile 32(M) x 64(N), K=256, on A[buf] ----
        float acc[2][8][4];
        #pragma unroll
        for (int mt = 0; mt < 2; mt++)
            #pragma unroll
            for (int nt = 0; nt < 8; nt++)
                #pragma unroll
                for (int f = 0; f < 4; f++) acc[mt][nt][f] = 0.f;

        uint32_t a_base = a_base0 + buf * a_stride_buf;
        #pragma unroll
        for (int kb = 0; kb < 16; kb++) {
            uint32_t a0, a1, a2, a3, a4, a5, a6, a7;
            ldsm4(a0, a1, a2, a3, a_base + kb * 32);
            ldsm4(a4, a5, a6, a7, a_base + 16 * RS * 2 + kb * 32);
            #pragma unroll
            for (int nt2 = 0; nt2 < 4; nt2++) {
                uint32_t b0, b1, b2, b3;
                ldsm4(b0, b1, b2, b3, b_base + nt2 * 16 * RS * 2 + kb * 32);
                mma16816(acc[0][2 * nt2],     a0, a1, a2, a3, b0, b1);
                mma16816(acc[0][2 * nt2 + 1], a0, a1, a2, a3, b2, b3);
                mma16816(acc[1][2 * nt2],     a4, a5, a6, a7, b0, b1);
                mma16816(acc[1][2 * nt2 + 1], a4, a5, a6, a7, b2, b3);
            }
        }

        // stage next tile into the OTHER buffer — no barrier needed vs MMA readers
        if (has_next) convertA(smem, buf ? SM_A0 : SM_A1, tid, pregs);

        // ---- epilogue: Student-t + row sums ----
        float* c2s = (float*)(smem + SM_C2);
        float rs[4] = {0.f, 0.f, 0.f, 0.f};
        #pragma unroll
        for (int mt = 0; mt < 2; mt++)
            #pragma unroll
            for (int nt = 0; nt < 8; nt++)
                #pragma unroll
                for (int f = 0; f < 4; f++) {
                    int hh = f >> 1, par = f & 1;
                    int col = wn * 64 + nt * 8 + tig * 2 + par;
                    float sse = fmaxf(fmaf(-2.f, acc[mt][nt][f],
                                           z2v[mt * 2 + hh] + c2s[col]), 0.f);
                    float v = __fdividef(1.f, 1.f + sse);
                    acc[mt][nt][f] = v;
                    rs[mt * 2 + hh] += v;
                }
        #pragma unroll
        for (int i = 0; i < 4; i++) {
            rs[i] += __shfl_xor_sync(0xffffffffu, rs[i], 1);
            rs[i] += __shfl_xor_sync(0xffffffffu, rs[i], 2);
        }
        float* rp = (float*)(smem + SM_ROWPART);
        if (tig == 0) {
            #pragma unroll
            for (int i = 0; i < 4; i++) {
                int mt = i >> 1, hh = i & 1;
                rp[wn * 64 + wm * 32 + mt * 16 + hh * 8 + g] = rs[i];
            }
        }
        __syncthreads();   // sync1: convertA(next) + rowpart visible

        if (tid < 64) {
            float s = rp[tid] + rp[64 + tid] + rp[128 + tid] + rp[192 + tid];
            ((float*)(smem + SM_RINV))[tid] = __fdividef(1.f, s);
        } else if (tid < 128 && has_next) {
            const float* z2p = (float*)(smem + SM_Z2P) + (tid - 64) * 65;
            float s = 0.f;
            #pragma unroll
            for (int c = 0; c < 64; c++) s += z2p[c];
            ((float*)(smem + SM_Z2))[(buf ^ 1) * 64 + (tid - 64)] = s;
        }
        __syncthreads();   // sync2: rinv + next z2 visible

        float* rinv_s = (float*)(smem + SM_RINV);
        float riv[4];
        #pragma unroll
        for (int i = 0; i < 4; i++) {
            int mt = i >> 1, hh = i & 1;
            riv[i] = rinv_s[wm * 32 + mt * 16 + hh * 8 + g];
        }

        // write normalized q + per-tile column partials
        float cp[16];
        #pragma unroll
        for (int j = 0; j < 16; j++) cp[j] = 0.f;

        float* qbase = out + (size_t)nrows * KCENT + (size_t)t * BM * KCENT;
        #pragma unroll
        for (int mt = 0; mt < 2; mt++)
            #pragma unroll
            for (int hh = 0; hh < 2; hh++) {
                int rloc = wm * 32 + mt * 16 + hh * 8 + g;
                float* qrow = qbase + (size_t)rloc * KCENT + wn * 64;
                float ri = riv[mt * 2 + hh];
                #pragma unroll
                for (int nt = 0; nt < 8; nt++) {
                    float2 v2;
                    v2.x = acc[mt][nt][hh * 2]     * ri;
                    v2.y = acc[mt][nt][hh * 2 + 1] * ri;
                    *(float2*)(qrow + nt * 8 + tig * 2) = v2;
                    cp[nt * 2]     += v2.x;
                    cp[nt * 2 + 1] += v2.y;
                }
            }
        #pragma unroll
        for (int j = 0; j < 16; j++) {
            cp[j] += __shfl_xor_sync(0xffffffffu, cp[j], 4);
            cp[j] += __shfl_xor_sync(0xffffffffu, cp[j], 8);
            cp[j] += __shfl_xor_sync(0xffffffffu, cp[j], 16);
        }
        // accumulate into smem colpart (disjoint addresses, writers only)
        float* cps = (float*)(smem + SM_COLPART);
        if (g == 0) {
            #pragma unroll
            for (int nt = 0; nt < 8; nt++) {
                int i0 = wm * 256 + wn * 64 + nt * 8 + tig * 2;
                cps[i0]     += cp[nt * 2];
                cps[i0 + 1] += cp[nt * 2 + 1];
            }
        }

        if (!has_next) break;
        t = tn;
        buf ^= 1;
    }

    __syncthreads();
    float* cps = (float*)(smem + SM_COLPART);
    g_partC[(size_t)tid * GRID1 + blockIdx.x] = cps[tid] + cps[256 + tid];
}

// ---------------- kernel 2: column-sum reduction (one warp per column) ----------------
__global__ void reduceT_kernel() {     // grid 32, 256 thr
    int w = threadIdx.x >> 5, lane = threadIdx.x & 31;
    int col = blockIdx.x * 8 + w;
    const float* src = g_partC + (size_t)col * GRID1;
    float s = 0.f;
    for (int j = lane; j < GRID1; j += 32) s += src[j];
    #pragma unroll
    for (int o = 16; o; o >>= 1) s += __shfl_xor_sync(0xffffffffu, s, o);
    if (lane == 0) g_rcol[col] = __fdividef(1.f, s);
}

// ---------------- kernel 3: p = rownorm(q^2 / colsum) ----------------
__global__ void __launch_bounds__(256) pass2_kernel(float* __restrict__ out, int nrows) {
    int tid = threadIdx.x, w = tid >> 5, lane = tid & 31;
    const float* q = out + (size_t)nrows * KCENT;
    float* p = out;
    float rcl[8];
    #pragma unroll
    for (int t = 0; t < 8; t++) rcl[t] = g_rcol[lane * 8 + t];

    size_t row0 = (size_t)blockIdx.x * 32 + w * 4;
    float4 a[4], b[4];
    #pragma unroll
    for (int i = 0; i < 4; i++) {
        const float4* qr = (const float4*)(q + (row0 + i) * KCENT);
        a[i] = __ldcs(qr + lane * 2);
        b[i] = __ldcs(qr + lane * 2 + 1);
    }
    float s[4];
    #pragma unroll
    for (int i = 0; i < 4; i++) {
        a[i].x = a[i].x * a[i].x * rcl[0];
        a[i].y = a[i].y * a[i].y * rcl[1];
        a[i].z = a[i].z * a[i].z * rcl[2];
        a[i].w = a[i].w * a[i].w * rcl[3];
        b[i].x = b[i].x * b[i].x * rcl[4];
        b[i].y = b[i].y * b[i].y * rcl[5];
        b[i].z = b[i].z * b[i].z * rcl[6];
        b[i].w = b[i].w * b[i].w * rcl[7];
        s[i] = ((a[i].x + a[i].y) + (a[i].z + a[i].w))
             + ((b[i].x + b[i].y) + (b[i].z + b[i].w));
    }
    #pragma unroll
    for (int o = 16; o; o >>= 1) {
        #pragma unroll
        for (int i = 0; i < 4; i++) s[i] += __shfl_xor_sync(0xffffffffu, s[i], o);
    }
    #pragma unroll
    for (int i = 0; i < 4; i++) {
        float rinv = __fdividef(1.f, s[i]);
        float4 pa, pb;
        pa.x = a[i].x * rinv; pa.y = a[i].y * rinv;
        pa.z = a[i].z * rinv; pa.w = a[i].w * rinv;
        pb.x = b[i].x * rinv; pb.y = b[i].y * rinv;
        pb.z = b[i].z * rinv; pb.w = b[i].w * rinv;
        float4* pr = (float4*)(p + (row0 + i) * KCENT);
        __stcs(pr + lane * 2, pa);
        __stcs(pr + lane * 2 + 1, pb);
    }
}

// ---------------- launch ----------------
extern "C" void kernel_launch(void* const* d_in, const int* in_sizes, int n_in,
                              void* d_out, int out_size) {
    const float* z = (const float*)d_in[0];
    const float* cent = (const float*)d_in[1];
    float* out = (float*)d_out;
    int nrows = in_sizes[0] / DDIM;          // 65536

    cudaFuncSetAttribute(pass1_kernel,
                         cudaFuncAttributeMaxDynamicSharedMemorySize, SMEM_TOTAL);

    prep_kernel<<<KCENT, 256>>>(cent);
    pass1_kernel<<<GRID1, NTHR, SMEM_TOTAL>>>(z, out, nrows);
    reduceT_kernel<<<32, 256>>>();
    pass2_kernel<<<nrows / 32, 256>>>(out, nrows);
}